// round 12
// baseline (speedup 1.0000x reference)
#include <cuda_runtime.h>

// TropicalLeNet fused, one launch. R12 = R11 minus unsupported min/max.f32x2:
// packed add.rn.f32x2 for the (x+w) pairs, scalar FMNMX on the halves.
// Shifted duplicate arrays make every x-pair one aligned LDS.64; weights
// stored pre-duplicated so (w,w) is one LDS.64 broadcast.

typedef unsigned long long ull;

__device__ __forceinline__ ull addx2(ull a, ull b) {
    ull r; asm("add.rn.f32x2 %0,%1,%2;" : "=l"(r) : "l"(a), "l"(b)); return r;
}
__device__ __forceinline__ float lo32(ull v) { return __uint_as_float((unsigned)v); }
__device__ __forceinline__ float hi32(ull v) { return __uint_as_float((unsigned)(v >> 32)); }

// Load the 5 consecutive column-pairs (c,c+1), c = 0..4 relative to an even
// base column: even-start pairs from E, odd-start pairs from the shifted copy O.
__device__ __forceinline__ void loadpairs(ull* P, const float* e, const float* o) {
    P[0] = *(const ull*)(e);
    P[1] = *(const ull*)(o);
    P[2] = *(const ull*)(e + 2);
    P[3] = *(const ull*)(o + 2);
    P[4] = *(const ull*)(e + 4);
}

__global__ void __launch_bounds__(512, 2)
lenet_kernel(const float* __restrict__ input,
             const float* __restrict__ w1,
             const float* __restrict__ w2,
             const float* __restrict__ fw1, const float* __restrict__ fb1,
             const float* __restrict__ fw2, const float* __restrict__ fb2,
             const float* __restrict__ fw3, const float* __restrict__ fb3,
             float* __restrict__ out)
{
    const int b   = blockIdx.x;
    const int tid = threadIdx.x;
    const int warp = tid >> 5, lane = tid & 31;

    __shared__ __align__(16) float xp [32 * 32];     // padded input
    __shared__ __align__(16) float xps[32 * 32];     // shifted: xps[r][c] = x[r][c+1]
    __shared__ __align__(16) float w1d[6 * 26 * 2];  // dup pairs (w,w)
    __shared__ __align__(16) float w2d[16 * 157 * 2];// dup pairs
    __shared__ __align__(16) float p1a[6 * 224];     // [ch]*224 + r*16 + col
    __shared__ __align__(16) float p1b[6 * 224];     // shifted copy
    __shared__ __align__(16) float p2s[400];
    __shared__ __align__(16) float h1[120];
    __shared__ __align__(16) float h2[84];

    // ---- stage 0: stage input (zero-padded, plus shifted copy) + weights ----
    {
        const float* inb = input + b * 784;
        #pragma unroll
        for (int k = 0; k < 2; k++) {
            int i = tid + 512 * k;
            int h = i >> 5, w = i & 31;
            bool in = (h >= 2) && (h < 30) && (w >= 2) && (w < 30);
            float v = in ? inb[(h - 2) * 28 + (w - 2)] : 0.0f;
            xp[i] = v;
            if (w > 0) xps[i - 1] = v;
        }
        if (tid < 150) {
            int ch = tid / 25, t = tid % 25;
            float v = w1[tid];
            int base = (ch * 26 + t) * 2;
            w1d[base] = v; w1d[base + 1] = v;
        }
        for (int i = tid; i < 2400; i += 512) {
            int f = i / 25, t = i % 25;           // f = oc*6 + c
            float v = w2[i];
            int base = ((f / 6) * 157 + (f % 6) * 26 + t) * 2;
            w2d[base] = v; w2d[base + 1] = v;
        }
    }
    __syncthreads();

    // ---- stage 1: min-plus conv1 + avgpool -> p1a/p1b ----
    // 392 threads: sp = tid%196, grp = tid/196 -> channels 3grp..3grp+2,
    // window rows streamed, shared across the 3 channels.
    if (tid < 392) {
        const int sp = tid % 196, grp = tid / 196;
        const int i = sp / 14, j = sp % 14;
        const float* eb = &xp [i * 64 + 2 * j];   // row r at eb + r*32
        const float* ob = &xps[i * 64 + 2 * j];
        const float* wb = &w1d[grp * 3 * 26 * 2];

        const float INF = __int_as_float(0x7f800000);
        float m00[3], m01[3], m10[3], m11[3];
        #pragma unroll
        for (int c = 0; c < 3; c++) {
            m00[c] = INF; m01[c] = INF; m10[c] = INF; m11[c] = INF;
        }

        ull A[5], B[5];
        loadpairs(A, eb, ob);                     // row 2i
        loadpairs(B, eb + 32, ob + 32);           // row 2i+1

        #define C1ROW(du, TOP, BOT)                                          \
            {                                                                \
                _Pragma("unroll")                                            \
                for (int c = 0; c < 3; c++) {                                \
                    const ull* wd = (const ull*)&wb[(c * 26 + (du) * 5) * 2];\
                    _Pragma("unroll")                                        \
                    for (int dv = 0; dv < 5; dv++) {                         \
                        ull wv = wd[dv];                                     \
                        ull st = addx2(TOP[dv], wv);                         \
                        ull sb = addx2(BOT[dv], wv);                         \
                        m00[c] = fminf(m00[c], lo32(st));                    \
                        m01[c] = fminf(m01[c], hi32(st));                    \
                        m10[c] = fminf(m10[c], lo32(sb));                    \
                        m11[c] = fminf(m11[c], hi32(sb));                    \
                    }                                                        \
                }                                                            \
            }

        C1ROW(0, A, B)
        loadpairs(A, eb + 2 * 32, ob + 2 * 32);
        C1ROW(1, B, A)
        loadpairs(B, eb + 3 * 32, ob + 3 * 32);
        C1ROW(2, A, B)
        loadpairs(A, eb + 4 * 32, ob + 4 * 32);
        C1ROW(3, B, A)
        loadpairs(B, eb + 5 * 32, ob + 5 * 32);
        C1ROW(4, A, B)
        #undef C1ROW

        #pragma unroll
        for (int c = 0; c < 3; c++) {
            float v = 0.25f * ((m00[c] + m01[c]) + (m10[c] + m11[c]));
            int ch = 3 * grp + c;
            p1a[ch * 224 + i * 16 + j] = v;
            if (j > 0) p1b[ch * 224 + i * 16 + j - 1] = v;
        }
    } else if (tid >= 416) {
        // warps 13-15: prefetch fw1 (1500 lines) + fw2 (315 lines) into L1.
        const int t = tid - 416;                  // 0..95
        #pragma unroll
        for (int k = 0; k < 16; k++) {
            int line = t * 16 + k;
            if (line < 1500) {
                const char* p = (const char*)fw1 + line * 128;
                asm volatile("prefetch.global.L1 [%0];" :: "l"(p));
            }
        }
        #pragma unroll
        for (int k = 0; k < 4; k++) {
            int line = t * 4 + k;
            if (line < 315) {
                const char* p = (const char*)fw2 + line * 128;
                asm volatile("prefetch.global.L1 [%0];" :: "l"(p));
            }
        }
    }
    __syncthreads();

    // ---- stage 2: max-plus conv2 + avgpool -> p2s[400] ----
    // oc = tid&15, sp = tid>>4 (sp<25 active); rows streamed per channel.
    {
        const int oc = tid & 15, sp = tid >> 4;
        if (sp < 25) {
            const int i = sp / 5, j = sp % 5;
            const float* wb = &w2d[oc * 157 * 2];
            const float NINF = __int_as_float(0xff800000);

            float acc = 0.0f;
            #pragma unroll 1
            for (int c = 0; c < 6; c++) {
                const float* eb = &p1a[c * 224 + i * 32 + 2 * j];
                const float* ob = &p1b[c * 224 + i * 32 + 2 * j];
                const ull* wc = (const ull*)&wb[c * 26 * 2];

                float m00 = NINF, m01 = NINF, m10 = NINF, m11 = NINF;
                ull A[5], B[5];
                loadpairs(A, eb, ob);             // row 2i
                loadpairs(B, eb + 16, ob + 16);   // row 2i+1

                #define C2ROW(du, TOP, BOT)                                 \
                    {                                                       \
                        const ull* wd = wc + (du) * 5;                      \
                        _Pragma("unroll")                                   \
                        for (int dv = 0; dv < 5; dv++) {                    \
                            ull wv = wd[dv];                                \
                            ull st = addx2(TOP[dv], wv);                    \
                            ull sb = addx2(BOT[dv], wv);                    \
                            m00 = fmaxf(m00, lo32(st));                     \
                            m01 = fmaxf(m01, hi32(st));                     \
                            m10 = fmaxf(m10, lo32(sb));                     \
                            m11 = fmaxf(m11, hi32(sb));                     \
                        }                                                   \
                    }

                C2ROW(0, A, B)
                loadpairs(A, eb + 2 * 16, ob + 2 * 16);
                C2ROW(1, B, A)
                loadpairs(B, eb + 3 * 16, ob + 3 * 16);
                C2ROW(2, A, B)
                loadpairs(A, eb + 4 * 16, ob + 4 * 16);
                C2ROW(3, B, A)
                loadpairs(B, eb + 5 * 16, ob + 5 * 16);
                C2ROW(4, A, B)
                #undef C2ROW

                acc += (m00 + m01) + (m10 + m11);
            }
            p2s[oc * 25 + sp] = 0.25f * acc;
        }
    }
    __syncthreads();

    // ---- fc1: 400 -> 120, relu. 60 output-pair tasks over 16 warps.
    for (int t = warp; t < 60; t += 16) {
        const int o0 = 2 * t, o1 = o0 + 1;
        const float4* wa = (const float4*)(fw1 + o0 * 400);
        const float4* wb = (const float4*)(fw1 + o1 * 400);
        const float4* xv = (const float4*)p2s;
        float sa = 0.0f, sb = 0.0f;
        #pragma unroll
        for (int k = 0; k < 3; k++) {
            const int i4 = lane + 32 * k;
            float4 v = xv[i4], a = wa[i4], c = wb[i4];
            sa = fmaf(v.x, a.x, sa); sa = fmaf(v.y, a.y, sa);
            sa = fmaf(v.z, a.z, sa); sa = fmaf(v.w, a.w, sa);
            sb = fmaf(v.x, c.x, sb); sb = fmaf(v.y, c.y, sb);
            sb = fmaf(v.z, c.z, sb); sb = fmaf(v.w, c.w, sb);
        }
        if (lane < 4) {
            const int i4 = 96 + lane;
            float4 v = xv[i4], a = wa[i4], c = wb[i4];
            sa = fmaf(v.x, a.x, sa); sa = fmaf(v.y, a.y, sa);
            sa = fmaf(v.z, a.z, sa); sa = fmaf(v.w, a.w, sa);
            sb = fmaf(v.x, c.x, sb); sb = fmaf(v.y, c.y, sb);
            sb = fmaf(v.z, c.z, sb); sb = fmaf(v.w, c.w, sb);
        }
        #pragma unroll
        for (int off = 16; off; off >>= 1) {
            sa += __shfl_xor_sync(0xffffffffu, sa, off);
            sb += __shfl_xor_sync(0xffffffffu, sb, off);
        }
        if (lane == 0) {
            h1[o0] = fmaxf(sa + fb1[o0], 0.0f);
            h1[o1] = fmaxf(sb + fb1[o1], 0.0f);
        }
    }
    __syncthreads();

    // ---- fc2: 120 -> 84, relu. 42 tasks; 30 float4/row.
    for (int t = warp; t < 42; t += 16) {
        const int o0 = 2 * t, o1 = o0 + 1;
        const float4* wa = (const float4*)(fw2 + o0 * 120);
        const float4* wb = (const float4*)(fw2 + o1 * 120);
        const float4* xv = (const float4*)h1;
        float sa = 0.0f, sb = 0.0f;
        if (lane < 30) {
            float4 v = xv[lane], a = wa[lane], c = wb[lane];
            sa = fmaf(v.x, a.x, sa); sa = fmaf(v.y, a.y, sa);
            sa = fmaf(v.z, a.z, sa); sa = fmaf(v.w, a.w, sa);
            sb = fmaf(v.x, c.x, sb); sb = fmaf(v.y, c.y, sb);
            sb = fmaf(v.z, c.z, sb); sb = fmaf(v.w, c.w, sb);
        }
        #pragma unroll
        for (int off = 16; off; off >>= 1) {
            sa += __shfl_xor_sync(0xffffffffu, sa, off);
            sb += __shfl_xor_sync(0xffffffffu, sb, off);
        }
        if (lane == 0) {
            h2[o0] = fmaxf(sa + fb2[o0], 0.0f);
            h2[o1] = fmaxf(sb + fb2[o1], 0.0f);
        }
    }
    __syncthreads();

    // ---- fc3: 84 -> 10. warps 0..9, one output each.
    if (warp < 10) {
        const int o = warp;
        const float4* wr = (const float4*)(fw3 + o * 84);
        const float4* xv = (const float4*)h2;
        float s = 0.0f;
        if (lane < 21) {
            float4 v = xv[lane], a = wr[lane];
            s = fmaf(v.x, a.x, s); s = fmaf(v.y, a.y, s);
            s = fmaf(v.z, a.z, s); s = fmaf(v.w, a.w, s);
        }
        #pragma unroll
        for (int off = 16; off; off >>= 1) s += __shfl_xor_sync(0xffffffffu, s, off);
        if (lane == 0) out[b * 10 + o] = s + fb3[o];
    }
}

extern "C" void kernel_launch(void* const* d_in, const int* in_sizes, int n_in,
                              void* d_out, int out_size)
{
    const float* input = (const float*)d_in[0];
    const float* w1    = (const float*)d_in[1];
    const float* w2    = (const float*)d_in[2];
    const float* fw1   = (const float*)d_in[3];
    const float* fb1   = (const float*)d_in[4];
    const float* fw2   = (const float*)d_in[5];
    const float* fb2   = (const float*)d_in[6];
    const float* fw3   = (const float*)d_in[7];
    const float* fb3   = (const float*)d_in[8];

    const int B = in_sizes[0] / 784;  // 256

    lenet_kernel<<<B, 512>>>(input, w1, w2, fw1, fb1, fw2, fb2, fw3, fb3,
                             (float*)d_out);
}

// round 13
// speedup vs baseline: 1.1105x; 1.1105x over previous
#include <cuda_runtime.h>

// TropicalLeNet fused, one launch. R13 = R9 base + conv2 channel-pairing:
// two channels (c, c+3) processed simultaneously -> 8 independent max-chains
// and two interleaved LDS row streams (2x per-warp ILP, same instr count).
// Weights read as inline broadcast LDS to keep regs under the 64 cap.

__device__ __forceinline__ void loadrow(float* dst, const float* p) {
    const float2* r = (const float2*)p;
    float2 a = r[0], b = r[1], c = r[2];
    dst[0] = a.x; dst[1] = a.y;
    dst[2] = b.x; dst[3] = b.y;
    dst[4] = c.x; dst[5] = c.y;
}

__global__ void __launch_bounds__(512, 2)
lenet_kernel(const float* __restrict__ input,
             const float* __restrict__ w1,
             const float* __restrict__ w2,
             const float* __restrict__ fw1, const float* __restrict__ fb1,
             const float* __restrict__ fw2, const float* __restrict__ fb2,
             const float* __restrict__ fw3, const float* __restrict__ fb3,
             float* __restrict__ out)
{
    const int b   = blockIdx.x;
    const int tid = threadIdx.x;
    const int warp = tid >> 5, lane = tid & 31;

    __shared__ __align__(16) float xp[32 * 34];     // padded input, stride 34
    __shared__ __align__(16) float w1s[6 * 28];     // [ch]*28 + t
    __shared__ __align__(16) float w2s[16 * 172];   // [oc]*172 + [c]*28 + t
    __shared__ __align__(16) float p1s[6 * 320];    // [c]*320 + r*22 + col
    __shared__ __align__(16) float p2s[400];
    __shared__ __align__(16) float h1[120];
    __shared__ __align__(16) float h2[84];

    // ---- stage 0: stage input (zero-padded) + conv weights ----
    {
        const float* inb = input + b * 784;
        #pragma unroll
        for (int k = 0; k < 2; k++) {
            int i = tid + 512 * k;
            int h = i >> 5, w = i & 31;
            bool in = (h >= 2) && (h < 30) && (w >= 2) && (w < 30);
            xp[h * 34 + w] = in ? inb[(h - 2) * 28 + (w - 2)] : 0.0f;
        }
        if (tid < 150) w1s[(tid / 25) * 28 + tid % 25] = w1[tid];
        for (int i = tid; i < 2400; i += 512) {
            int f = i / 25, t = i % 25;           // f = oc*6 + c
            w2s[(f / 6) * 172 + (f % 6) * 28 + t] = w2[i];
        }
    }
    __syncthreads();

    // ---- stage 1: min-plus conv1 + avgpool -> p1s ----
    // 392 threads: sp = tid%196, cg = tid/196 -> channels 3cg..3cg+2.
    if (tid < 392) {
        const int sp = tid % 196, cg = tid / 196;
        const int i = sp / 14, j = sp % 14;
        const float* rbase = &xp[i * 68 + 2 * j];  // row r at rbase + r*34

        #pragma unroll 1
        for (int cc = 0; cc < 3; cc++) {
            const int ch = 3 * cg + cc;
            float wr[25];
            {
                const float4* wq = (const float4*)&w1s[ch * 28];
                #pragma unroll
                for (int q = 0; q < 6; q++) {
                    float4 v = wq[q];
                    wr[4 * q]     = v.x; wr[4 * q + 1] = v.y;
                    wr[4 * q + 2] = v.z; wr[4 * q + 3] = v.w;
                }
                wr[24] = w1s[ch * 28 + 24];
            }

            float ra[6], rb[6], rc[6];
            loadrow(ra, rbase);
            loadrow(rb, rbase + 34);

            const float INF = __int_as_float(0x7f800000);
            float m00 = INF, m01 = INF, m10 = INF, m11 = INF;

            #define C1TAPS(du, X, Y)                                        \
                {                                                           \
                    _Pragma("unroll")                                       \
                    for (int dv = 0; dv < 5; dv++) {                        \
                        const float w = wr[(du) * 5 + dv];                  \
                        m00 = fminf(m00, X[dv]     + w);                    \
                        m01 = fminf(m01, X[dv + 1] + w);                    \
                        m10 = fminf(m10, Y[dv]     + w);                    \
                        m11 = fminf(m11, Y[dv + 1] + w);                    \
                    }                                                       \
                }

            loadrow(rc, rbase + 2 * 34);
            C1TAPS(0, ra, rb)
            loadrow(ra, rbase + 3 * 34);
            C1TAPS(1, rb, rc)
            loadrow(rb, rbase + 4 * 34);
            C1TAPS(2, rc, ra)
            loadrow(rc, rbase + 5 * 34);
            C1TAPS(3, ra, rb)
            C1TAPS(4, rb, rc)
            #undef C1TAPS

            p1s[ch * 320 + i * 22 + j] = 0.25f * ((m00 + m01) + (m10 + m11));
        }
    } else if (tid >= 416) {
        // warps 13-15: prefetch fw1 (1500 lines) + fw2 (315 lines) into L1.
        const int t = tid - 416;                  // 0..95
        #pragma unroll
        for (int k = 0; k < 16; k++) {
            int line = t * 16 + k;
            if (line < 1500) {
                const char* p = (const char*)fw1 + line * 128;
                asm volatile("prefetch.global.L1 [%0];" :: "l"(p));
            }
        }
        #pragma unroll
        for (int k = 0; k < 4; k++) {
            int line = t * 4 + k;
            if (line < 315) {
                const char* p = (const char*)fw2 + line * 128;
                asm volatile("prefetch.global.L1 [%0];" :: "l"(p));
            }
        }
    }
    __syncthreads();

    // ---- stage 2: max-plus conv2 + avgpool -> p2s[400] ----
    // oc = tid&15, sp = tid>>4 (sp<25 active). Channel PAIRS (cc, cc+3):
    // 8 independent chains, interleaved row streams.
    {
        const int oc = tid & 15, sp = tid >> 4;
        if (sp < 25) {
            const int i = sp / 5, j = sp % 5;
            const float* wbase = &w2s[oc * 172];
            const float NINF = __int_as_float(0xff800000);

            float accA = 0.0f, accB = 0.0f;
            #pragma unroll 1
            for (int cc = 0; cc < 3; cc++) {
                const float* wA = wbase + cc * 28;
                const float* wB = wbase + (cc + 3) * 28;
                const float* pA = &p1s[cc * 320 + i * 44 + 2 * j];
                const float* pB = &p1s[(cc + 3) * 320 + i * 44 + 2 * j];

                float a0[6], a1[6], a2[6];
                float b0[6], b1[6], b2[6];
                loadrow(a0, pA);         loadrow(b0, pB);
                loadrow(a1, pA + 22);    loadrow(b1, pB + 22);

                float A00 = NINF, A01 = NINF, A10 = NINF, A11 = NINF;
                float B00 = NINF, B01 = NINF, B10 = NINF, B11 = NINF;

                #define C2ROW(du, XA, YA, XB, YB)                           \
                    {                                                       \
                        _Pragma("unroll")                                   \
                        for (int dv = 0; dv < 5; dv++) {                    \
                            const float wa = wA[(du) * 5 + dv];             \
                            const float wb = wB[(du) * 5 + dv];             \
                            A00 = fmaxf(A00, XA[dv]     + wa);              \
                            A01 = fmaxf(A01, XA[dv + 1] + wa);              \
                            A10 = fmaxf(A10, YA[dv]     + wa);              \
                            A11 = fmaxf(A11, YA[dv + 1] + wa);              \
                            B00 = fmaxf(B00, XB[dv]     + wb);              \
                            B01 = fmaxf(B01, XB[dv + 1] + wb);              \
                            B10 = fmaxf(B10, YB[dv]     + wb);              \
                            B11 = fmaxf(B11, YB[dv + 1] + wb);              \
                        }                                                   \
                    }

                loadrow(a2, pA + 44);    loadrow(b2, pB + 44);
                C2ROW(0, a0, a1, b0, b1)
                loadrow(a0, pA + 66);    loadrow(b0, pB + 66);
                C2ROW(1, a1, a2, b1, b2)
                loadrow(a1, pA + 88);    loadrow(b1, pB + 88);
                C2ROW(2, a2, a0, b2, b0)
                loadrow(a2, pA + 110);   loadrow(b2, pB + 110);
                C2ROW(3, a0, a1, b0, b1)
                C2ROW(4, a1, a2, b1, b2)
                #undef C2ROW

                accA += (A00 + A01) + (A10 + A11);
                accB += (B00 + B01) + (B10 + B11);
            }
            p2s[oc * 25 + sp] = 0.25f * (accA + accB);
        }
    }
    __syncthreads();

    // ---- fc1: 400 -> 120, relu. 60 output-pair tasks over 16 warps.
    for (int t = warp; t < 60; t += 16) {
        const int o0 = 2 * t, o1 = o0 + 1;
        const float4* wa = (const float4*)(fw1 + o0 * 400);
        const float4* wb = (const float4*)(fw1 + o1 * 400);
        const float4* xv = (const float4*)p2s;
        float sa = 0.0f, sb = 0.0f;
        #pragma unroll
        for (int k = 0; k < 3; k++) {
            const int i4 = lane + 32 * k;
            float4 v = xv[i4], a = wa[i4], c = wb[i4];
            sa = fmaf(v.x, a.x, sa); sa = fmaf(v.y, a.y, sa);
            sa = fmaf(v.z, a.z, sa); sa = fmaf(v.w, a.w, sa);
            sb = fmaf(v.x, c.x, sb); sb = fmaf(v.y, c.y, sb);
            sb = fmaf(v.z, c.z, sb); sb = fmaf(v.w, c.w, sb);
        }
        if (lane < 4) {
            const int i4 = 96 + lane;
            float4 v = xv[i4], a = wa[i4], c = wb[i4];
            sa = fmaf(v.x, a.x, sa); sa = fmaf(v.y, a.y, sa);
            sa = fmaf(v.z, a.z, sa); sa = fmaf(v.w, a.w, sa);
            sb = fmaf(v.x, c.x, sb); sb = fmaf(v.y, c.y, sb);
            sb = fmaf(v.z, c.z, sb); sb = fmaf(v.w, c.w, sb);
        }
        #pragma unroll
        for (int off = 16; off; off >>= 1) {
            sa += __shfl_xor_sync(0xffffffffu, sa, off);
            sb += __shfl_xor_sync(0xffffffffu, sb, off);
        }
        if (lane == 0) {
            h1[o0] = fmaxf(sa + fb1[o0], 0.0f);
            h1[o1] = fmaxf(sb + fb1[o1], 0.0f);
        }
    }
    __syncthreads();

    // ---- fc2: 120 -> 84, relu. 42 tasks; 30 float4/row.
    for (int t = warp; t < 42; t += 16) {
        const int o0 = 2 * t, o1 = o0 + 1;
        const float4* wa = (const float4*)(fw2 + o0 * 120);
        const float4* wb = (const float4*)(fw2 + o1 * 120);
        const float4* xv = (const float4*)h1;
        float sa = 0.0f, sb = 0.0f;
        if (lane < 30) {
            float4 v = xv[lane], a = wa[lane], c = wb[lane];
            sa = fmaf(v.x, a.x, sa); sa = fmaf(v.y, a.y, sa);
            sa = fmaf(v.z, a.z, sa); sa = fmaf(v.w, a.w, sa);
            sb = fmaf(v.x, c.x, sb); sb = fmaf(v.y, c.y, sb);
            sb = fmaf(v.z, c.z, sb); sb = fmaf(v.w, c.w, sb);
        }
        #pragma unroll
        for (int off = 16; off; off >>= 1) {
            sa += __shfl_xor_sync(0xffffffffu, sa, off);
            sb += __shfl_xor_sync(0xffffffffu, sb, off);
        }
        if (lane == 0) {
            h2[o0] = fmaxf(sa + fb2[o0], 0.0f);
            h2[o1] = fmaxf(sb + fb2[o1], 0.0f);
        }
    }
    __syncthreads();

    // ---- fc3: 84 -> 10. warps 0..9, one output each.
    if (warp < 10) {
        const int o = warp;
        const float4* wr = (const float4*)(fw3 + o * 84);
        const float4* xv = (const float4*)h2;
        float s = 0.0f;
        if (lane < 21) {
            float4 v = xv[lane], a = wr[lane];
            s = fmaf(v.x, a.x, s); s = fmaf(v.y, a.y, s);
            s = fmaf(v.z, a.z, s); s = fmaf(v.w, a.w, s);
        }
        #pragma unroll
        for (int off = 16; off; off >>= 1) s += __shfl_xor_sync(0xffffffffu, s, off);
        if (lane == 0) out[b * 10 + o] = s + fb3[o];
    }
}

extern "C" void kernel_launch(void* const* d_in, const int* in_sizes, int n_in,
                              void* d_out, int out_size)
{
    const float* input = (const float*)d_in[0];
    const float* w1    = (const float*)d_in[1];
    const float* w2    = (const float*)d_in[2];
    const float* fw1   = (const float*)d_in[3];
    const float* fb1   = (const float*)d_in[4];
    const float* fw2   = (const float*)d_in[5];
    const float* fb2   = (const float*)d_in[6];
    const float* fw3   = (const float*)d_in[7];
    const float* fb3   = (const float*)d_in[8];

    const int B = in_sizes[0] / 784;  // 256

    lenet_kernel<<<B, 512>>>(input, w1, w2, fw1, fb1, fw2, fb2, fw3, fb3,
                             (float*)d_out);
}